// round 1
// baseline (speedup 1.0000x reference)
#include <cuda_runtime.h>

#define NN 50000
#define EE 250000
#define HD 64

// persistent scratch (no allocations allowed)
__device__ float g_x[2][(size_t)NN * HD];   // double-buffered node state
__device__ float g_y[(size_t)EE * HD];      // edge state
__device__ float g_goal[16];                // goal node feature vec (9 used)

__device__ __forceinline__ void atomicMaxF(float* addr, float v) {
    if (v >= 0.f) atomicMax((int*)addr, __float_as_int(v));
    else          atomicMin((unsigned int*)addr, __float_as_uint(v));
}

// ---------------------------------------------------------------------------
// goal = vc[argmax(labels[:,1])]  (first index on ties)
// ---------------------------------------------------------------------------
__global__ void k_goal(const float* __restrict__ v,
                       const float* __restrict__ labels, int n) {
    __shared__ float bv[1024];
    __shared__ int   bi[1024];
    float best = -1e30f; int bidx = 0;
    for (int i = threadIdx.x; i < n; i += 1024) {
        float val = labels[2 * i + 1];
        if (val > best) { best = val; bidx = i; }
    }
    bv[threadIdx.x] = best; bi[threadIdx.x] = bidx;
    __syncthreads();
    for (int s = 512; s > 0; s >>= 1) {
        if (threadIdx.x < s) {
            float ov = bv[threadIdx.x + s]; int oi = bi[threadIdx.x + s];
            if (ov > bv[threadIdx.x] || (ov == bv[threadIdx.x] && oi < bi[threadIdx.x])) {
                bv[threadIdx.x] = ov; bi[threadIdx.x] = oi;
            }
        }
        __syncthreads();
    }
    if (threadIdx.x == 0) {
        int g = bi[0];
        #pragma unroll
        for (int c = 0; c < 7; c++) g_goal[c] = v[g * 7 + c];
        g_goal[7] = labels[2 * g];
        g_goal[8] = labels[2 * g + 1];
    }
}

// ---------------------------------------------------------------------------
// x0 = MLP_hx([vc, goal, d, d*d])   (36 -> 64 -> 64), 4 nodes/block
// ---------------------------------------------------------------------------
__global__ void k_x0(const float* __restrict__ v, const float* __restrict__ labels,
                     const float* __restrict__ w1, const float* __restrict__ b1,
                     const float* __restrict__ w2, const float* __restrict__ b2, int n) {
    __shared__ float in_s[4][36];
    __shared__ float h_s[4][64];
    int g = threadIdx.x >> 6, j = threadIdx.x & 63;
    int node = blockIdx.x * 4 + g;
    bool act = node < n;
    if (act && j < 9) {
        float vc = (j < 7) ? v[node * 7 + j] : labels[node * 2 + (j - 7)];
        float gl = g_goal[j];
        float d  = vc - gl;
        in_s[g][j]      = vc;
        in_s[g][9 + j]  = gl;
        in_s[g][18 + j] = d;
        in_s[g][27 + j] = d * d;
    }
    __syncthreads();
    if (act) {
        float acc = b1[j];
        #pragma unroll
        for (int k = 0; k < 36; k++) acc = fmaf(in_s[g][k], w1[k * 64 + j], acc);
        h_s[g][j] = fmaxf(acc, 0.f);
    }
    __syncthreads();
    if (act) {
        float acc = b2[j];
        #pragma unroll
        for (int k = 0; k < 64; k++) acc = fmaf(h_s[g][k], w2[k * 64 + j], acc);
        g_x[0][(size_t)node * 64 + j] = acc;
    }
}

// ---------------------------------------------------------------------------
// y0 = MLP_hy([vj - vi, vj, vi])  (27 -> 64 -> 64), vi = vc[src], vj = vc[dst]
// 4 edges/block
// ---------------------------------------------------------------------------
__global__ void k_y0(const float* __restrict__ v, const float* __restrict__ labels,
                     const int* __restrict__ ei,
                     const float* __restrict__ w1, const float* __restrict__ b1,
                     const float* __restrict__ w2, const float* __restrict__ b2, int ne) {
    __shared__ float in_s[4][27];
    __shared__ float h_s[4][64];
    int g = threadIdx.x >> 6, j = threadIdx.x & 63;
    int e = blockIdx.x * 4 + g;
    bool act = e < ne;
    if (act && j < 9) {
        int s = ei[e], d = ei[ne + e];
        float vi = (j < 7) ? v[s * 7 + j] : labels[s * 2 + (j - 7)];
        float vj = (j < 7) ? v[d * 7 + j] : labels[d * 2 + (j - 7)];
        in_s[g][j]      = vj - vi;
        in_s[g][9 + j]  = vj;
        in_s[g][18 + j] = vi;
    }
    __syncthreads();
    if (act) {
        float acc = b1[j];
        #pragma unroll
        for (int k = 0; k < 27; k++) acc = fmaf(in_s[g][k], w1[k * 64 + j], acc);
        h_s[g][j] = fmaxf(acc, 0.f);
    }
    __syncthreads();
    if (act) {
        float acc = b2[j];
        #pragma unroll
        for (int k = 0; k < 64; k++) acc = fmaf(h_s[g][k], w2[k * 64 + j], acc);
        g_y[(size_t)e * 64 + j] = acc;
    }
}

// ---------------------------------------------------------------------------
// copy x buffer (init for scatter-max)
// ---------------------------------------------------------------------------
__global__ void k_copy(int from, int to, int n4) {
    int i = blockIdx.x * blockDim.x + threadIdx.x;
    if (i < n4) ((float4*)g_x[to])[i] = ((const float4*)g_x[from])[i];
}

// ---------------------------------------------------------------------------
// fx: m = MLP_fx([x[src]-x[dst], x[src], x[dst], y]) (256->64->64)
//     then atomicMax into xnew[dst].  16 edges/block, 16 thr/edge, 4 cols/thr
// ---------------------------------------------------------------------------
#define FX_STRIDE 260
#define H_STRIDE  68
__global__ __launch_bounds__(256) void k_fx(
        const int* __restrict__ ei,
        const float* __restrict__ w1, const float* __restrict__ b1,
        const float* __restrict__ w2, const float* __restrict__ b2,
        int rbuf, int wbuf, int ne) {
    __shared__ float in_s[16 * FX_STRIDE];
    __shared__ float h_s[16 * H_STRIDE];
    int g = threadIdx.x >> 4, t = threadIdx.x & 15;
    int e = blockIdx.x * 16 + g;
    const float* xr = g_x[rbuf];
    float*       xw = g_x[wbuf];
    int s = ei[e], d = ei[ne + e];
    float4 xa = *(const float4*)(xr + (size_t)s * 64 + 4 * t);   // xj = x[src]
    float4 xb = *(const float4*)(xr + (size_t)d * 64 + 4 * t);   // xi = x[dst]
    float4 yv = *(const float4*)(g_y + (size_t)e * 64 + 4 * t);
    float* ine = in_s + g * FX_STRIDE;
    *(float4*)(ine + 4 * t)       = make_float4(xa.x - xb.x, xa.y - xb.y, xa.z - xb.z, xa.w - xb.w);
    *(float4*)(ine + 64 + 4 * t)  = xa;
    *(float4*)(ine + 128 + 4 * t) = xb;
    *(float4*)(ine + 192 + 4 * t) = yv;
    __syncthreads();

    const float4* w1v = (const float4*)w1;
    float4 acc = *(const float4*)(b1 + 4 * t);
    #pragma unroll 8
    for (int k = 0; k < 256; k++) {
        float sv = ine[k];
        float4 w = w1v[k * 16 + t];
        acc.x = fmaf(sv, w.x, acc.x);
        acc.y = fmaf(sv, w.y, acc.y);
        acc.z = fmaf(sv, w.z, acc.z);
        acc.w = fmaf(sv, w.w, acc.w);
    }
    float* he = h_s + g * H_STRIDE;
    *(float4*)(he + 4 * t) = make_float4(fmaxf(acc.x, 0.f), fmaxf(acc.y, 0.f),
                                         fmaxf(acc.z, 0.f), fmaxf(acc.w, 0.f));
    __syncthreads();

    const float4* w2v = (const float4*)w2;
    float4 o = *(const float4*)(b2 + 4 * t);
    #pragma unroll 8
    for (int k = 0; k < 64; k++) {
        float sv = he[k];
        float4 w = w2v[k * 16 + t];
        o.x = fmaf(sv, w.x, o.x);
        o.y = fmaf(sv, w.y, o.y);
        o.z = fmaf(sv, w.z, o.z);
        o.w = fmaf(sv, w.w, o.w);
    }
    float* dp = xw + (size_t)d * 64 + 4 * t;
    atomicMaxF(dp + 0, o.x);
    atomicMaxF(dp + 1, o.y);
    atomicMaxF(dp + 2, o.z);
    atomicMaxF(dp + 3, o.w);
}

// ---------------------------------------------------------------------------
// fy: y = max(y, MLP_fy([x[dst]-x[src], x[dst], x[src]]))  (192->64->64)
//     (reference: xi = x[src], xj = x[dst], input = [xj-xi, xj, xi])
// ---------------------------------------------------------------------------
#define FY_STRIDE 196
__global__ __launch_bounds__(256) void k_fy(
        const int* __restrict__ ei,
        const float* __restrict__ w1, const float* __restrict__ b1,
        const float* __restrict__ w2, const float* __restrict__ b2,
        int buf, int ne) {
    __shared__ float in_s[16 * FY_STRIDE];
    __shared__ float h_s[16 * H_STRIDE];
    int g = threadIdx.x >> 4, t = threadIdx.x & 15;
    int e = blockIdx.x * 16 + g;
    const float* xr = g_x[buf];
    int s = ei[e], d = ei[ne + e];
    float4 xj = *(const float4*)(xr + (size_t)d * 64 + 4 * t);   // xj = x[dst]
    float4 xi = *(const float4*)(xr + (size_t)s * 64 + 4 * t);   // xi = x[src]
    float* ine = in_s + g * FY_STRIDE;
    *(float4*)(ine + 4 * t)       = make_float4(xj.x - xi.x, xj.y - xi.y, xj.z - xi.z, xj.w - xi.w);
    *(float4*)(ine + 64 + 4 * t)  = xj;
    *(float4*)(ine + 128 + 4 * t) = xi;
    __syncthreads();

    const float4* w1v = (const float4*)w1;
    float4 acc = *(const float4*)(b1 + 4 * t);
    #pragma unroll 8
    for (int k = 0; k < 192; k++) {
        float sv = ine[k];
        float4 w = w1v[k * 16 + t];
        acc.x = fmaf(sv, w.x, acc.x);
        acc.y = fmaf(sv, w.y, acc.y);
        acc.z = fmaf(sv, w.z, acc.z);
        acc.w = fmaf(sv, w.w, acc.w);
    }
    float* he = h_s + g * H_STRIDE;
    *(float4*)(he + 4 * t) = make_float4(fmaxf(acc.x, 0.f), fmaxf(acc.y, 0.f),
                                         fmaxf(acc.z, 0.f), fmaxf(acc.w, 0.f));
    __syncthreads();

    const float4* w2v = (const float4*)w2;
    float4 o = *(const float4*)(b2 + 4 * t);
    #pragma unroll 8
    for (int k = 0; k < 64; k++) {
        float sv = he[k];
        float4 w = w2v[k * 16 + t];
        o.x = fmaf(sv, w.x, o.x);
        o.y = fmaf(sv, w.y, o.y);
        o.z = fmaf(sv, w.z, o.z);
        o.w = fmaf(sv, w.w, o.w);
    }
    float* yp = g_y + (size_t)e * 64 + 4 * t;
    yp[0] = fmaxf(yp[0], o.x);
    yp[1] = fmaxf(yp[1], o.y);
    yp[2] = fmaxf(yp[2], o.z);
    yp[3] = fmaxf(yp[3], o.w);
}

// ---------------------------------------------------------------------------
// head: out = w3^T relu(w2^T relu(w1^T x + b1) + b2)    4 nodes/block
// ---------------------------------------------------------------------------
__global__ void k_out(const float* __restrict__ w1, const float* __restrict__ b1,
                      const float* __restrict__ w2, const float* __restrict__ b2,
                      const float* __restrict__ w3, float* __restrict__ out,
                      int buf, int n) {
    __shared__ float x_s[4][64];
    __shared__ float h_s[4][64];
    __shared__ float p_s[4][64];
    int g = threadIdx.x >> 6, j = threadIdx.x & 63;
    int node = blockIdx.x * 4 + g;
    bool act = node < n;
    if (act) x_s[g][j] = g_x[buf][(size_t)node * 64 + j];
    __syncthreads();
    if (act) {
        float acc = b1[j];
        #pragma unroll
        for (int k = 0; k < 64; k++) acc = fmaf(x_s[g][k], w1[k * 64 + j], acc);
        h_s[g][j] = fmaxf(acc, 0.f);
    }
    __syncthreads();
    if (act) {
        float acc = b2[j];
        #pragma unroll
        for (int k = 0; k < 64; k++) acc = fmaf(h_s[g][k], w2[k * 64 + j], acc);
        p_s[g][j] = fmaxf(acc, 0.f) * w3[j];
    }
    __syncthreads();
    if (act && j == 0) {
        float sum = 0.f;
        #pragma unroll
        for (int k = 0; k < 64; k++) sum += p_s[g][k];
        out[node] = sum;
    }
}

// ---------------------------------------------------------------------------
extern "C" void kernel_launch(void* const* d_in, const int* in_sizes, int n_in,
                              void* d_out, int out_size) {
    const float* v      = (const float*)d_in[0];
    const float* labels = (const float*)d_in[1];
    const int*   ei     = (const int*)d_in[2];
    // d_in[3] = loop (fixed at 3; unrolled below)
    const float *hx_w1 = (const float*)d_in[4],  *hx_b1 = (const float*)d_in[5];
    const float *hx_w2 = (const float*)d_in[6],  *hx_b2 = (const float*)d_in[7];
    const float *hy_w1 = (const float*)d_in[8],  *hy_b1 = (const float*)d_in[9];
    const float *hy_w2 = (const float*)d_in[10], *hy_b2 = (const float*)d_in[11];
    const float *fx_w1 = (const float*)d_in[12], *fx_b1 = (const float*)d_in[13];
    const float *fx_w2 = (const float*)d_in[14], *fx_b2 = (const float*)d_in[15];
    const float *fy_w1 = (const float*)d_in[16], *fy_b1 = (const float*)d_in[17];
    const float *fy_w2 = (const float*)d_in[18], *fy_b2 = (const float*)d_in[19];
    const float *fe_w1 = (const float*)d_in[20], *fe_b1 = (const float*)d_in[21];
    const float *fe_w2 = (const float*)d_in[22], *fe_b2 = (const float*)d_in[23];
    const float *fe_w3 = (const float*)d_in[24];

    int n  = in_sizes[0] / 7;       // 50000
    int ne = in_sizes[2] / 2;       // 250000
    float* out = (float*)d_out;

    k_goal<<<1, 1024>>>(v, labels, n);
    k_x0<<<(n + 3) / 4, 256>>>(v, labels, hx_w1, hx_b1, hx_w2, hx_b2, n);
    k_y0<<<(ne + 3) / 4, 256>>>(v, labels, ei, hy_w1, hy_b1, hy_w2, hy_b2, ne);

    int copy_blocks = (n * 16 + 255) / 256;    // n*64/4 float4s
    int eb = ne / 16;                           // 15625 blocks

    // iter 1: x_a(0) -> x_b(1)
    k_copy<<<copy_blocks, 256>>>(0, 1, n * 16);
    k_fx<<<eb, 256>>>(ei, fx_w1, fx_b1, fx_w2, fx_b2, 0, 1, ne);
    k_fy<<<eb, 256>>>(ei, fy_w1, fy_b1, fy_w2, fy_b2, 1, ne);
    // iter 2: x_b(1) -> x_a(0)
    k_copy<<<copy_blocks, 256>>>(1, 0, n * 16);
    k_fx<<<eb, 256>>>(ei, fx_w1, fx_b1, fx_w2, fx_b2, 1, 0, ne);
    k_fy<<<eb, 256>>>(ei, fy_w1, fy_b1, fy_w2, fy_b2, 0, ne);
    // iter 3: x_a(0) -> x_b(1)
    k_copy<<<copy_blocks, 256>>>(0, 1, n * 16);
    k_fx<<<eb, 256>>>(ei, fx_w1, fx_b1, fx_w2, fx_b2, 0, 1, ne);
    k_fy<<<eb, 256>>>(ei, fy_w1, fy_b1, fy_w2, fy_b2, 1, ne);

    k_out<<<(n + 3) / 4, 256>>>(fe_w1, fe_b1, fe_w2, fe_b2, fe_w3, out, 1, n);
}

// round 2
// speedup vs baseline: 1.5458x; 1.5458x over previous
#include <cuda_runtime.h>

#define NN 50000
#define EE 250000
#define HD 64

// persistent scratch (no allocations allowed)
__device__ float g_x[2][(size_t)NN * HD];   // double-buffered node state
__device__ float g_y[(size_t)EE * HD];      // edge state
__device__ float g_goal[16];                // goal node feature vec (9 used)

__device__ __forceinline__ void atomicMaxF(float* addr, float v) {
    if (v >= 0.f) atomicMax((int*)addr, __float_as_int(v));
    else          atomicMin((unsigned int*)addr, __float_as_uint(v));
}

// ---------------------------------------------------------------------------
// goal = vc[argmax(labels[:,1])]  (first index on ties)
// ---------------------------------------------------------------------------
__global__ void k_goal(const float* __restrict__ v,
                       const float* __restrict__ labels, int n) {
    __shared__ float bv[1024];
    __shared__ int   bi[1024];
    float best = -1e30f; int bidx = 0;
    for (int i = threadIdx.x; i < n; i += 1024) {
        float val = labels[2 * i + 1];
        if (val > best) { best = val; bidx = i; }
    }
    bv[threadIdx.x] = best; bi[threadIdx.x] = bidx;
    __syncthreads();
    for (int s = 512; s > 0; s >>= 1) {
        if (threadIdx.x < s) {
            float ov = bv[threadIdx.x + s]; int oi = bi[threadIdx.x + s];
            if (ov > bv[threadIdx.x] || (ov == bv[threadIdx.x] && oi < bi[threadIdx.x])) {
                bv[threadIdx.x] = ov; bi[threadIdx.x] = oi;
            }
        }
        __syncthreads();
    }
    if (threadIdx.x == 0) {
        int g = bi[0];
        #pragma unroll
        for (int c = 0; c < 7; c++) g_goal[c] = v[g * 7 + c];
        g_goal[7] = labels[2 * g];
        g_goal[8] = labels[2 * g + 1];
    }
}

// ---------------------------------------------------------------------------
// x0 = MLP_hx([vc, goal, d, d*d])   (36 -> 64 -> 64), 4 nodes/block
// ---------------------------------------------------------------------------
__global__ void k_x0(const float* __restrict__ v, const float* __restrict__ labels,
                     const float* __restrict__ w1, const float* __restrict__ b1,
                     const float* __restrict__ w2, const float* __restrict__ b2, int n) {
    __shared__ float in_s[4][36];
    __shared__ float h_s[4][64];
    int g = threadIdx.x >> 6, j = threadIdx.x & 63;
    int node = blockIdx.x * 4 + g;
    if (j < 9) {
        float vc = (j < 7) ? v[node * 7 + j] : labels[node * 2 + (j - 7)];
        float gl = g_goal[j];
        float d  = vc - gl;
        in_s[g][j]      = vc;
        in_s[g][9 + j]  = gl;
        in_s[g][18 + j] = d;
        in_s[g][27 + j] = d * d;
    }
    __syncthreads();
    {
        float acc = b1[j];
        #pragma unroll
        for (int k = 0; k < 36; k++) acc = fmaf(in_s[g][k], w1[k * 64 + j], acc);
        h_s[g][j] = fmaxf(acc, 0.f);
    }
    __syncthreads();
    {
        float acc = b2[j];
        #pragma unroll
        for (int k = 0; k < 64; k++) acc = fmaf(h_s[g][k], w2[k * 64 + j], acc);
        g_x[0][(size_t)node * 64 + j] = acc;
    }
}

// ---------------------------------------------------------------------------
// y0 = MLP_hy([vj - vi, vj, vi])  (27 -> 64 -> 64), vi = vc[src], vj = vc[dst]
// 16 edges/block, 16 threads/edge, 4 cols/thread  (ne divisible by 16)
// ---------------------------------------------------------------------------
__global__ __launch_bounds__(256) void k_y0(
        const float* __restrict__ v, const float* __restrict__ labels,
        const int* __restrict__ ei,
        const float* __restrict__ w1, const float* __restrict__ b1,
        const float* __restrict__ w2, const float* __restrict__ b2, int ne) {
    __shared__ float in_s[16][28];
    __shared__ float h_s[16][68];
    int g = threadIdx.x >> 4, tt = threadIdx.x & 15;
    int e = blockIdx.x * 16 + g;
    if (tt < 9) {
        int s = ei[e], d = ei[ne + e];
        float vi = (tt < 7) ? v[s * 7 + tt] : labels[s * 2 + (tt - 7)];
        float vj = (tt < 7) ? v[d * 7 + tt] : labels[d * 2 + (tt - 7)];
        in_s[g][tt]      = vj - vi;
        in_s[g][9 + tt]  = vj;
        in_s[g][18 + tt] = vi;
    }
    __syncthreads();
    const float4* w1v = (const float4*)w1;
    float4 acc = *(const float4*)(b1 + 4 * tt);
    #pragma unroll
    for (int k = 0; k < 27; k++) {
        float sv = in_s[g][k];
        float4 w = w1v[k * 16 + tt];
        acc.x = fmaf(sv, w.x, acc.x);
        acc.y = fmaf(sv, w.y, acc.y);
        acc.z = fmaf(sv, w.z, acc.z);
        acc.w = fmaf(sv, w.w, acc.w);
    }
    *(float4*)(&h_s[g][4 * tt]) = make_float4(fmaxf(acc.x, 0.f), fmaxf(acc.y, 0.f),
                                              fmaxf(acc.z, 0.f), fmaxf(acc.w, 0.f));
    __syncthreads();
    const float4* w2v = (const float4*)w2;
    float4 o = *(const float4*)(b2 + 4 * tt);
    #pragma unroll 8
    for (int k = 0; k < 64; k++) {
        float sv = h_s[g][k];
        float4 w = w2v[k * 16 + tt];
        o.x = fmaf(sv, w.x, o.x);
        o.y = fmaf(sv, w.y, o.y);
        o.z = fmaf(sv, w.z, o.z);
        o.w = fmaf(sv, w.w, o.w);
    }
    *(float4*)(g_y + (size_t)e * 64 + 4 * tt) = o;
}

// ---------------------------------------------------------------------------
// copy x buffer (init for scatter-max)
// ---------------------------------------------------------------------------
__global__ void k_copy(int from, int to, int n4) {
    int i = blockIdx.x * blockDim.x + threadIdx.x;
    if (i < n4) ((float4*)g_x[to])[i] = ((const float4*)g_x[from])[i];
}

// ---------------------------------------------------------------------------
// k_fx: m = MLP_fx([x[src]-x[dst], x[src], x[dst], y]) (256->64->64)
//       atomicMax into xnew[dst].
// Block: 32 edges x 64 outs, 128 threads, 4x4 register tile per thread.
// Inputs staged transposed: in_t[k][edge]  (stride 36 for alignment)
// ---------------------------------------------------------------------------
#define TS 36
__global__ __launch_bounds__(128) void k_fx(
        const int* __restrict__ ei,
        const float* __restrict__ w1, const float* __restrict__ b1,
        const float* __restrict__ w2, const float* __restrict__ b2,
        int rbuf, int wbuf, int ne) {
    __shared__ float in_t[256 * TS];
    __shared__ float h_t[64 * TS];
    int t = threadIdx.x;
    int q = t >> 5, el = t & 31;
    int e = blockIdx.x * 32 + el;
    const float* xr = g_x[rbuf];
    float*       xw = g_x[wbuf];
    bool act = e < ne;
    int s = act ? ei[e] : 0;
    int d = act ? ei[ne + e] : 0;

    // fill transposed inputs: seg0 = xs-xd, seg1 = xs, seg2 = xd, seg3 = y
    if (q == 0) {
        const float4* a = (const float4*)(xr + (size_t)s * 64);
        const float4* b = (const float4*)(xr + (size_t)d * 64);
        #pragma unroll
        for (int r = 0; r < 16; r++) {
            float4 va = act ? a[r] : make_float4(0, 0, 0, 0);
            float4 vb = act ? b[r] : make_float4(0, 0, 0, 0);
            in_t[(4 * r + 0) * TS + el] = va.x - vb.x;
            in_t[(4 * r + 1) * TS + el] = va.y - vb.y;
            in_t[(4 * r + 2) * TS + el] = va.z - vb.z;
            in_t[(4 * r + 3) * TS + el] = va.w - vb.w;
        }
    } else {
        const float4* p;
        if (q == 1)      p = (const float4*)(xr + (size_t)s * 64);
        else if (q == 2) p = (const float4*)(xr + (size_t)d * 64);
        else             p = (const float4*)(g_y + (size_t)e * 64);
        int base = q * 64;
        #pragma unroll
        for (int r = 0; r < 16; r++) {
            float4 v = act ? p[r] : make_float4(0, 0, 0, 0);
            in_t[(base + 4 * r + 0) * TS + el] = v.x;
            in_t[(base + 4 * r + 1) * TS + el] = v.y;
            in_t[(base + 4 * r + 2) * TS + el] = v.z;
            in_t[(base + 4 * r + 3) * TS + el] = v.w;
        }
    }
    __syncthreads();

    int i = t & 7;    // edge group: edges 4i..4i+3
    int j = t >> 3;   // out group:  outs  4j..4j+3  (0..15)
    float acc[4][4];
    {
        float4 bv = *(const float4*)(b1 + 4 * j);
        #pragma unroll
        for (int ii = 0; ii < 4; ii++) {
            acc[ii][0] = bv.x; acc[ii][1] = bv.y; acc[ii][2] = bv.z; acc[ii][3] = bv.w;
        }
    }
    #pragma unroll 4
    for (int k = 0; k < 256; k++) {
        float4 ev = *(const float4*)(&in_t[k * TS + 4 * i]);
        float4 wv = __ldg((const float4*)(w1 + k * 64 + 4 * j));
        acc[0][0] = fmaf(ev.x, wv.x, acc[0][0]); acc[0][1] = fmaf(ev.x, wv.y, acc[0][1]);
        acc[0][2] = fmaf(ev.x, wv.z, acc[0][2]); acc[0][3] = fmaf(ev.x, wv.w, acc[0][3]);
        acc[1][0] = fmaf(ev.y, wv.x, acc[1][0]); acc[1][1] = fmaf(ev.y, wv.y, acc[1][1]);
        acc[1][2] = fmaf(ev.y, wv.z, acc[1][2]); acc[1][3] = fmaf(ev.y, wv.w, acc[1][3]);
        acc[2][0] = fmaf(ev.z, wv.x, acc[2][0]); acc[2][1] = fmaf(ev.z, wv.y, acc[2][1]);
        acc[2][2] = fmaf(ev.z, wv.z, acc[2][2]); acc[2][3] = fmaf(ev.z, wv.w, acc[2][3]);
        acc[3][0] = fmaf(ev.w, wv.x, acc[3][0]); acc[3][1] = fmaf(ev.w, wv.y, acc[3][1]);
        acc[3][2] = fmaf(ev.w, wv.z, acc[3][2]); acc[3][3] = fmaf(ev.w, wv.w, acc[3][3]);
    }
    // relu, store hidden transposed: h_t[out_k][edge]
    #pragma unroll
    for (int jj = 0; jj < 4; jj++)
        #pragma unroll
        for (int ii = 0; ii < 4; ii++)
            h_t[(4 * j + jj) * TS + 4 * i + ii] = fmaxf(acc[ii][jj], 0.f);
    __syncthreads();

    {
        float4 bv = *(const float4*)(b2 + 4 * j);
        #pragma unroll
        for (int ii = 0; ii < 4; ii++) {
            acc[ii][0] = bv.x; acc[ii][1] = bv.y; acc[ii][2] = bv.z; acc[ii][3] = bv.w;
        }
    }
    #pragma unroll 4
    for (int k = 0; k < 64; k++) {
        float4 ev = *(const float4*)(&h_t[k * TS + 4 * i]);
        float4 wv = __ldg((const float4*)(w2 + k * 64 + 4 * j));
        acc[0][0] = fmaf(ev.x, wv.x, acc[0][0]); acc[0][1] = fmaf(ev.x, wv.y, acc[0][1]);
        acc[0][2] = fmaf(ev.x, wv.z, acc[0][2]); acc[0][3] = fmaf(ev.x, wv.w, acc[0][3]);
        acc[1][0] = fmaf(ev.y, wv.x, acc[1][0]); acc[1][1] = fmaf(ev.y, wv.y, acc[1][1]);
        acc[1][2] = fmaf(ev.y, wv.z, acc[1][2]); acc[1][3] = fmaf(ev.y, wv.w, acc[1][3]);
        acc[2][0] = fmaf(ev.z, wv.x, acc[2][0]); acc[2][1] = fmaf(ev.z, wv.y, acc[2][1]);
        acc[2][2] = fmaf(ev.z, wv.z, acc[2][2]); acc[2][3] = fmaf(ev.z, wv.w, acc[2][3]);
        acc[3][0] = fmaf(ev.w, wv.x, acc[3][0]); acc[3][1] = fmaf(ev.w, wv.y, acc[3][1]);
        acc[3][2] = fmaf(ev.w, wv.z, acc[3][2]); acc[3][3] = fmaf(ev.w, wv.w, acc[3][3]);
    }
    #pragma unroll
    for (int ii = 0; ii < 4; ii++) {
        int eg = blockIdx.x * 32 + 4 * i + ii;
        if (eg < ne) {
            int dd = ei[ne + eg];
            float* dp = xw + (size_t)dd * 64 + 4 * j;
            atomicMaxF(dp + 0, acc[ii][0]);
            atomicMaxF(dp + 1, acc[ii][1]);
            atomicMaxF(dp + 2, acc[ii][2]);
            atomicMaxF(dp + 3, acc[ii][3]);
        }
    }
}

// ---------------------------------------------------------------------------
// k_fy: y = max(y, MLP_fy([x[dst]-x[src], x[dst], x[src]]))  (192->64->64)
// Same tiling as k_fx.
// ---------------------------------------------------------------------------
__global__ __launch_bounds__(128) void k_fy(
        const int* __restrict__ ei,
        const float* __restrict__ w1, const float* __restrict__ b1,
        const float* __restrict__ w2, const float* __restrict__ b2,
        int buf, int ne) {
    __shared__ float in_t[192 * TS];
    __shared__ float h_t[64 * TS];
    int t = threadIdx.x;
    int q = t >> 5, el = t & 31;
    int e = blockIdx.x * 32 + el;
    const float* xr = g_x[buf];
    bool act = e < ne;
    int s = act ? ei[e] : 0;
    int d = act ? ei[ne + e] : 0;

    // seg0 = xj - xi = x[dst]-x[src], seg1 = x[dst], seg2 = x[src]
    if (q == 0) {
        const float4* a = (const float4*)(xr + (size_t)d * 64);
        const float4* b = (const float4*)(xr + (size_t)s * 64);
        #pragma unroll
        for (int r = 0; r < 16; r++) {
            float4 va = act ? a[r] : make_float4(0, 0, 0, 0);
            float4 vb = act ? b[r] : make_float4(0, 0, 0, 0);
            in_t[(4 * r + 0) * TS + el] = va.x - vb.x;
            in_t[(4 * r + 1) * TS + el] = va.y - vb.y;
            in_t[(4 * r + 2) * TS + el] = va.z - vb.z;
            in_t[(4 * r + 3) * TS + el] = va.w - vb.w;
        }
    } else if (q < 3) {
        const float4* p = (const float4*)(xr + (size_t)(q == 1 ? d : s) * 64);
        int base = q * 64;
        #pragma unroll
        for (int r = 0; r < 16; r++) {
            float4 v = act ? p[r] : make_float4(0, 0, 0, 0);
            in_t[(base + 4 * r + 0) * TS + el] = v.x;
            in_t[(base + 4 * r + 1) * TS + el] = v.y;
            in_t[(base + 4 * r + 2) * TS + el] = v.z;
            in_t[(base + 4 * r + 3) * TS + el] = v.w;
        }
    }
    __syncthreads();

    int i = t & 7;
    int j = t >> 3;
    float acc[4][4];
    {
        float4 bv = *(const float4*)(b1 + 4 * j);
        #pragma unroll
        for (int ii = 0; ii < 4; ii++) {
            acc[ii][0] = bv.x; acc[ii][1] = bv.y; acc[ii][2] = bv.z; acc[ii][3] = bv.w;
        }
    }
    #pragma unroll 4
    for (int k = 0; k < 192; k++) {
        float4 ev = *(const float4*)(&in_t[k * TS + 4 * i]);
        float4 wv = __ldg((const float4*)(w1 + k * 64 + 4 * j));
        acc[0][0] = fmaf(ev.x, wv.x, acc[0][0]); acc[0][1] = fmaf(ev.x, wv.y, acc[0][1]);
        acc[0][2] = fmaf(ev.x, wv.z, acc[0][2]); acc[0][3] = fmaf(ev.x, wv.w, acc[0][3]);
        acc[1][0] = fmaf(ev.y, wv.x, acc[1][0]); acc[1][1] = fmaf(ev.y, wv.y, acc[1][1]);
        acc[1][2] = fmaf(ev.y, wv.z, acc[1][2]); acc[1][3] = fmaf(ev.y, wv.w, acc[1][3]);
        acc[2][0] = fmaf(ev.z, wv.x, acc[2][0]); acc[2][1] = fmaf(ev.z, wv.y, acc[2][1]);
        acc[2][2] = fmaf(ev.z, wv.z, acc[2][2]); acc[2][3] = fmaf(ev.z, wv.w, acc[2][3]);
        acc[3][0] = fmaf(ev.w, wv.x, acc[3][0]); acc[3][1] = fmaf(ev.w, wv.y, acc[3][1]);
        acc[3][2] = fmaf(ev.w, wv.z, acc[3][2]); acc[3][3] = fmaf(ev.w, wv.w, acc[3][3]);
    }
    #pragma unroll
    for (int jj = 0; jj < 4; jj++)
        #pragma unroll
        for (int ii = 0; ii < 4; ii++)
            h_t[(4 * j + jj) * TS + 4 * i + ii] = fmaxf(acc[ii][jj], 0.f);
    __syncthreads();

    {
        float4 bv = *(const float4*)(b2 + 4 * j);
        #pragma unroll
        for (int ii = 0; ii < 4; ii++) {
            acc[ii][0] = bv.x; acc[ii][1] = bv.y; acc[ii][2] = bv.z; acc[ii][3] = bv.w;
        }
    }
    #pragma unroll 4
    for (int k = 0; k < 64; k++) {
        float4 ev = *(const float4*)(&h_t[k * TS + 4 * i]);
        float4 wv = __ldg((const float4*)(w2 + k * 64 + 4 * j));
        acc[0][0] = fmaf(ev.x, wv.x, acc[0][0]); acc[0][1] = fmaf(ev.x, wv.y, acc[0][1]);
        acc[0][2] = fmaf(ev.x, wv.z, acc[0][2]); acc[0][3] = fmaf(ev.x, wv.w, acc[0][3]);
        acc[1][0] = fmaf(ev.y, wv.x, acc[1][0]); acc[1][1] = fmaf(ev.y, wv.y, acc[1][1]);
        acc[1][2] = fmaf(ev.y, wv.z, acc[1][2]); acc[1][3] = fmaf(ev.y, wv.w, acc[1][3]);
        acc[2][0] = fmaf(ev.z, wv.x, acc[2][0]); acc[2][1] = fmaf(ev.z, wv.y, acc[2][1]);
        acc[2][2] = fmaf(ev.z, wv.z, acc[2][2]); acc[2][3] = fmaf(ev.z, wv.w, acc[2][3]);
        acc[3][0] = fmaf(ev.w, wv.x, acc[3][0]); acc[3][1] = fmaf(ev.w, wv.y, acc[3][1]);
        acc[3][2] = fmaf(ev.w, wv.z, acc[3][2]); acc[3][3] = fmaf(ev.w, wv.w, acc[3][3]);
    }
    #pragma unroll
    for (int ii = 0; ii < 4; ii++) {
        int eg = blockIdx.x * 32 + 4 * i + ii;
        if (eg < ne) {
            float4* yp = (float4*)(g_y + (size_t)eg * 64 + 4 * j);
            float4 old = *yp;
            old.x = fmaxf(old.x, acc[ii][0]);
            old.y = fmaxf(old.y, acc[ii][1]);
            old.z = fmaxf(old.z, acc[ii][2]);
            old.w = fmaxf(old.w, acc[ii][3]);
            *yp = old;
        }
    }
}

// ---------------------------------------------------------------------------
// head: out = w3^T relu(w2^T relu(w1^T x + b1) + b2)    4 nodes/block
// ---------------------------------------------------------------------------
__global__ void k_out(const float* __restrict__ w1, const float* __restrict__ b1,
                      const float* __restrict__ w2, const float* __restrict__ b2,
                      const float* __restrict__ w3, float* __restrict__ out,
                      int buf, int n) {
    __shared__ float x_s[4][64];
    __shared__ float h_s[4][64];
    __shared__ float p_s[4][64];
    int g = threadIdx.x >> 6, j = threadIdx.x & 63;
    int node = blockIdx.x * 4 + g;
    x_s[g][j] = g_x[buf][(size_t)node * 64 + j];
    __syncthreads();
    {
        float acc = b1[j];
        #pragma unroll
        for (int k = 0; k < 64; k++) acc = fmaf(x_s[g][k], w1[k * 64 + j], acc);
        h_s[g][j] = fmaxf(acc, 0.f);
    }
    __syncthreads();
    {
        float acc = b2[j];
        #pragma unroll
        for (int k = 0; k < 64; k++) acc = fmaf(h_s[g][k], w2[k * 64 + j], acc);
        p_s[g][j] = fmaxf(acc, 0.f) * w3[j];
    }
    __syncthreads();
    if (j == 0) {
        float sum = 0.f;
        #pragma unroll
        for (int k = 0; k < 64; k++) sum += p_s[g][k];
        out[node] = sum;
    }
}

// ---------------------------------------------------------------------------
extern "C" void kernel_launch(void* const* d_in, const int* in_sizes, int n_in,
                              void* d_out, int out_size) {
    const float* v      = (const float*)d_in[0];
    const float* labels = (const float*)d_in[1];
    const int*   ei     = (const int*)d_in[2];
    // d_in[3] = loop (fixed at 3; unrolled below)
    const float *hx_w1 = (const float*)d_in[4],  *hx_b1 = (const float*)d_in[5];
    const float *hx_w2 = (const float*)d_in[6],  *hx_b2 = (const float*)d_in[7];
    const float *hy_w1 = (const float*)d_in[8],  *hy_b1 = (const float*)d_in[9];
    const float *hy_w2 = (const float*)d_in[10], *hy_b2 = (const float*)d_in[11];
    const float *fx_w1 = (const float*)d_in[12], *fx_b1 = (const float*)d_in[13];
    const float *fx_w2 = (const float*)d_in[14], *fx_b2 = (const float*)d_in[15];
    const float *fy_w1 = (const float*)d_in[16], *fy_b1 = (const float*)d_in[17];
    const float *fy_w2 = (const float*)d_in[18], *fy_b2 = (const float*)d_in[19];
    const float *fe_w1 = (const float*)d_in[20], *fe_b1 = (const float*)d_in[21];
    const float *fe_w2 = (const float*)d_in[22], *fe_b2 = (const float*)d_in[23];
    const float *fe_w3 = (const float*)d_in[24];

    int n  = in_sizes[0] / 7;       // 50000
    int ne = in_sizes[2] / 2;       // 250000
    float* out = (float*)d_out;

    k_goal<<<1, 1024>>>(v, labels, n);
    k_x0<<<n / 4, 256>>>(v, labels, hx_w1, hx_b1, hx_w2, hx_b2, n);
    k_y0<<<ne / 16, 256>>>(v, labels, ei, hy_w1, hy_b1, hy_w2, hy_b2, ne);

    int copy_blocks = (n * 16 + 255) / 256;    // n*64/4 float4s
    int eb = (ne + 31) / 32;                    // 7813 blocks

    // iter 1: x_a(0) -> x_b(1)
    k_copy<<<copy_blocks, 256>>>(0, 1, n * 16);
    k_fx<<<eb, 128>>>(ei, fx_w1, fx_b1, fx_w2, fx_b2, 0, 1, ne);
    k_fy<<<eb, 128>>>(ei, fy_w1, fy_b1, fy_w2, fy_b2, 1, ne);
    // iter 2: x_b(1) -> x_a(0)
    k_copy<<<copy_blocks, 256>>>(1, 0, n * 16);
    k_fx<<<eb, 128>>>(ei, fx_w1, fx_b1, fx_w2, fx_b2, 1, 0, ne);
    k_fy<<<eb, 128>>>(ei, fy_w1, fy_b1, fy_w2, fy_b2, 0, ne);
    // iter 3: x_a(0) -> x_b(1)
    k_copy<<<copy_blocks, 256>>>(0, 1, n * 16);
    k_fx<<<eb, 128>>>(ei, fx_w1, fx_b1, fx_w2, fx_b2, 0, 1, ne);
    k_fy<<<eb, 128>>>(ei, fy_w1, fy_b1, fy_w2, fy_b2, 1, ne);

    k_out<<<n / 4, 256>>>(fe_w1, fe_b1, fe_w2, fe_b2, fe_w3, out, 1, n);
}

// round 3
// speedup vs baseline: 1.9820x; 1.2822x over previous
#include <cuda_runtime.h>

#define NN 50000
#define EE 250000
#define HD 64

// persistent scratch (no allocations allowed)
__device__ float g_x[2][(size_t)NN * HD];   // double-buffered node state
__device__ float g_y[(size_t)EE * HD];      // edge state
__device__ float g_goal[16];                // goal node feature vec (9 used)

// precombined weights (difference segments folded in)
__device__ float g_wfx[192 * 64];           // [xs, xd, y]
__device__ float g_wfy[128 * 64];           // [xj, xi]
__device__ float g_why[18 * 64];            // [vj, vi]
__device__ float g_whx[18 * 64];            // [vc, d*d]
__device__ float g_bhx[64];                 // hx bias + goal fold

__device__ __forceinline__ void atomicMaxF(float* addr, float v) {
    if (v >= 0.f) atomicMax((int*)addr, __float_as_int(v));
    else          atomicMin((unsigned int*)addr, __float_as_uint(v));
}

// ---------------------------------------------------------------------------
// goal = vc[argmax(labels[:,1])]  (first index on ties)
// ---------------------------------------------------------------------------
__global__ void k_goal(const float* __restrict__ v,
                       const float* __restrict__ labels, int n) {
    __shared__ float bv[1024];
    __shared__ int   bi[1024];
    float best = -1e30f; int bidx = 0;
    for (int i = threadIdx.x; i < n; i += 1024) {
        float val = labels[2 * i + 1];
        if (val > best) { best = val; bidx = i; }
    }
    bv[threadIdx.x] = best; bi[threadIdx.x] = bidx;
    __syncthreads();
    for (int s = 512; s > 0; s >>= 1) {
        if (threadIdx.x < s) {
            float ov = bv[threadIdx.x + s]; int oi = bi[threadIdx.x + s];
            if (ov > bv[threadIdx.x] || (ov == bv[threadIdx.x] && oi < bi[threadIdx.x])) {
                bv[threadIdx.x] = ov; bi[threadIdx.x] = oi;
            }
        }
        __syncthreads();
    }
    if (threadIdx.x == 0) {
        int g = bi[0];
        #pragma unroll
        for (int c = 0; c < 7; c++) g_goal[c] = v[g * 7 + c];
        g_goal[7] = labels[2 * g];
        g_goal[8] = labels[2 * g + 1];
    }
}

// ---------------------------------------------------------------------------
// weight precombination kernels
// fx: [d, xs, xd, y]@W -> [xs, xd, y]:  Wxs=W[64:128]+W[0:64], Wxd=W[128:192]-W[0:64], Wy=W[192:256]
// ---------------------------------------------------------------------------
__global__ void k_prep_fx(const float* __restrict__ w1) {
    int idx = blockIdx.x * 256 + threadIdx.x;
    if (idx >= 192 * 64) return;
    int k = idx >> 6, j = idx & 63;
    float o;
    if (k < 64)       o = w1[(64 + k) * 64 + j] + w1[k * 64 + j];
    else if (k < 128) o = w1[(64 + k) * 64 + j] - w1[(k - 64) * 64 + j];
    else              o = w1[(64 + k) * 64 + j];
    g_wfx[idx] = o;
}
// fy: [xj-xi, xj, xi]@W -> [xj, xi]:  Wxj=W[0:64]+W[64:128], Wxi=W[128:192]-W[0:64]
__global__ void k_prep_fy(const float* __restrict__ w1) {
    int idx = blockIdx.x * 256 + threadIdx.x;
    if (idx >= 128 * 64) return;
    int k = idx >> 6, j = idx & 63;
    float o;
    if (k < 64) o = w1[k * 64 + j] + w1[(64 + k) * 64 + j];
    else        o = w1[(64 + k) * 64 + j] - w1[(k - 64) * 64 + j];
    g_wfy[idx] = o;
}
// hy: [vj-vi, vj, vi] -> [vj, vi]; hx: [vc, goal, d, dd] -> [vc, dd] + bias fold
__global__ void k_prep_h(const float* __restrict__ hyw1,
                         const float* __restrict__ hxw1,
                         const float* __restrict__ hxb1) {
    int idx = blockIdx.x * 64 + threadIdx.x;
    if (idx < 1152) {                       // hy combined 18x64
        int k = idx >> 6, j = idx & 63;
        float o;
        if (k < 9) o = hyw1[k * 64 + j] + hyw1[(9 + k) * 64 + j];
        else       o = hyw1[(9 + k) * 64 + j] - hyw1[(k - 9) * 64 + j];
        g_why[idx] = o;
    } else if (idx < 2304) {                // hx combined 18x64
        int r = idx - 1152;
        int k = r >> 6, j = r & 63;
        float o;
        if (k < 9) o = hxw1[k * 64 + j] + hxw1[(18 + k) * 64 + j];
        else       o = hxw1[(18 + k) * 64 + j];   // dd rows = W[27:36], (27+k-9)=18+k
        g_whx[r] = o;
    } else if (idx < 2368) {                // hx bias fold: b + goal@(Wg - Wd)
        int j = idx - 2304;
        float acc = hxb1[j];
        #pragma unroll
        for (int c = 0; c < 9; c++)
            acc += g_goal[c] * (hxw1[(9 + c) * 64 + j] - hxw1[(18 + c) * 64 + j]);
        g_bhx[j] = acc;
    }
}

// ---------------------------------------------------------------------------
// x0 = MLP_hx: combined input [vc, d*d]  (18 -> 64 -> 64), 4 nodes/block
// ---------------------------------------------------------------------------
__global__ void k_x0(const float* __restrict__ v, const float* __restrict__ labels,
                     const float* __restrict__ w2, const float* __restrict__ b2, int n) {
    __shared__ float in_s[4][18];
    __shared__ float h_s[4][64];
    int g = threadIdx.x >> 6, j = threadIdx.x & 63;
    int node = blockIdx.x * 4 + g;
    if (j < 9) {
        float vc = (j < 7) ? v[node * 7 + j] : labels[node * 2 + (j - 7)];
        float d  = vc - g_goal[j];
        in_s[g][j]     = vc;
        in_s[g][9 + j] = d * d;
    }
    __syncthreads();
    {
        float acc = g_bhx[j];
        #pragma unroll
        for (int k = 0; k < 18; k++) acc = fmaf(in_s[g][k], g_whx[k * 64 + j], acc);
        h_s[g][j] = fmaxf(acc, 0.f);
    }
    __syncthreads();
    {
        float acc = b2[j];
        #pragma unroll
        for (int k = 0; k < 64; k++) acc = fmaf(h_s[g][k], w2[k * 64 + j], acc);
        g_x[0][(size_t)node * 64 + j] = acc;
    }
}

// ---------------------------------------------------------------------------
// y0 = MLP_hy: combined input [vj, vi] (18 -> 64 -> 64)
// 16 edges/block, 16 threads/edge, 4 cols/thread
// ---------------------------------------------------------------------------
__global__ __launch_bounds__(256) void k_y0(
        const float* __restrict__ v, const float* __restrict__ labels,
        const int* __restrict__ ei,
        const float* __restrict__ b1,
        const float* __restrict__ w2, const float* __restrict__ b2, int ne) {
    __shared__ float in_s[16][20];
    __shared__ float h_s[16][68];
    int g = threadIdx.x >> 4, tt = threadIdx.x & 15;
    int e = blockIdx.x * 16 + g;
    if (tt < 9) {
        int s = ei[e], d = ei[ne + e];
        float vi = (tt < 7) ? v[s * 7 + tt] : labels[s * 2 + (tt - 7)];
        float vj = (tt < 7) ? v[d * 7 + tt] : labels[d * 2 + (tt - 7)];
        in_s[g][tt]     = vj;
        in_s[g][9 + tt] = vi;
    }
    __syncthreads();
    const float4* w1v = (const float4*)g_why;
    float4 acc = *(const float4*)(b1 + 4 * tt);
    #pragma unroll
    for (int k = 0; k < 18; k++) {
        float sv = in_s[g][k];
        float4 w = w1v[k * 16 + tt];
        acc.x = fmaf(sv, w.x, acc.x);
        acc.y = fmaf(sv, w.y, acc.y);
        acc.z = fmaf(sv, w.z, acc.z);
        acc.w = fmaf(sv, w.w, acc.w);
    }
    *(float4*)(&h_s[g][4 * tt]) = make_float4(fmaxf(acc.x, 0.f), fmaxf(acc.y, 0.f),
                                              fmaxf(acc.z, 0.f), fmaxf(acc.w, 0.f));
    __syncthreads();
    const float4* w2v = (const float4*)w2;
    float4 o = *(const float4*)(b2 + 4 * tt);
    #pragma unroll 8
    for (int k = 0; k < 64; k++) {
        float sv = h_s[g][k];
        float4 w = w2v[k * 16 + tt];
        o.x = fmaf(sv, w.x, o.x);
        o.y = fmaf(sv, w.y, o.y);
        o.z = fmaf(sv, w.z, o.z);
        o.w = fmaf(sv, w.w, o.w);
    }
    *(float4*)(g_y + (size_t)e * 64 + 4 * tt) = o;
}

// ---------------------------------------------------------------------------
// copy x buffer (init for scatter-max)
// ---------------------------------------------------------------------------
__global__ void k_copy(int from, int to, int n4) {
    int i = blockIdx.x * blockDim.x + threadIdx.x;
    if (i < n4) ((float4*)g_x[to])[i] = ((const float4*)g_x[from])[i];
}

// ---------------------------------------------------------------------------
// k_fx: m = MLP_fx combined input [xs, xd, y] (192->64->64), atomicMax to xnew[dst]
// Block: 32 edges x 64 outs, 128 threads, 4x4 register tile / thread.
// Transposed staging in_t[k][edge] (stride 36).
// ---------------------------------------------------------------------------
#define TS 36
__global__ __launch_bounds__(128) void k_fx(
        const int* __restrict__ ei,
        const float* __restrict__ b1,
        const float* __restrict__ w2, const float* __restrict__ b2,
        int rbuf, int wbuf, int ne) {
    __shared__ float in_t[192 * TS];
    __shared__ float h_t[64 * TS];
    int t = threadIdx.x;
    int q = t >> 5, el = t & 31;
    int e = blockIdx.x * 32 + el;
    const float* xr = g_x[rbuf];
    float*       xw = g_x[wbuf];
    bool act = e < ne;
    int s = act ? ei[e] : 0;
    int d = act ? ei[ne + e] : 0;

    const float4* ps = (const float4*)(xr + (size_t)s * 64);
    const float4* pd = (const float4*)(xr + (size_t)d * 64);
    const float4* py = (const float4*)(g_y + (size_t)e * 64);
    // 48 float4-chunks (3 segments x 16), warp q handles chunks 12q..12q+11
    #pragma unroll
    for (int c0 = 0; c0 < 12; c0++) {
        int c = q * 12 + c0;
        int seg = c >> 4, r = c & 15;
        const float4* p = (seg == 0) ? ps : (seg == 1) ? pd : py;
        float4 vv = act ? p[r] : make_float4(0, 0, 0, 0);
        int base = seg * 64 + 4 * r;
        in_t[(base + 0) * TS + el] = vv.x;
        in_t[(base + 1) * TS + el] = vv.y;
        in_t[(base + 2) * TS + el] = vv.z;
        in_t[(base + 3) * TS + el] = vv.w;
    }
    __syncthreads();

    int i = t & 7;    // edge group: edges 4i..4i+3
    int j = t >> 3;   // out group:  outs  4j..4j+3
    float acc[4][4];
    {
        float4 bv = *(const float4*)(b1 + 4 * j);
        #pragma unroll
        for (int ii = 0; ii < 4; ii++) {
            acc[ii][0] = bv.x; acc[ii][1] = bv.y; acc[ii][2] = bv.z; acc[ii][3] = bv.w;
        }
    }
    #pragma unroll 4
    for (int k = 0; k < 192; k++) {
        float4 ev = *(const float4*)(&in_t[k * TS + 4 * i]);
        float4 wv = __ldg((const float4*)(g_wfx + k * 64 + 4 * j));
        acc[0][0] = fmaf(ev.x, wv.x, acc[0][0]); acc[0][1] = fmaf(ev.x, wv.y, acc[0][1]);
        acc[0][2] = fmaf(ev.x, wv.z, acc[0][2]); acc[0][3] = fmaf(ev.x, wv.w, acc[0][3]);
        acc[1][0] = fmaf(ev.y, wv.x, acc[1][0]); acc[1][1] = fmaf(ev.y, wv.y, acc[1][1]);
        acc[1][2] = fmaf(ev.y, wv.z, acc[1][2]); acc[1][3] = fmaf(ev.y, wv.w, acc[1][3]);
        acc[2][0] = fmaf(ev.z, wv.x, acc[2][0]); acc[2][1] = fmaf(ev.z, wv.y, acc[2][1]);
        acc[2][2] = fmaf(ev.z, wv.z, acc[2][2]); acc[2][3] = fmaf(ev.z, wv.w, acc[2][3]);
        acc[3][0] = fmaf(ev.w, wv.x, acc[3][0]); acc[3][1] = fmaf(ev.w, wv.y, acc[3][1]);
        acc[3][2] = fmaf(ev.w, wv.z, acc[3][2]); acc[3][3] = fmaf(ev.w, wv.w, acc[3][3]);
    }
    #pragma unroll
    for (int jj = 0; jj < 4; jj++)
        #pragma unroll
        for (int ii = 0; ii < 4; ii++)
            h_t[(4 * j + jj) * TS + 4 * i + ii] = fmaxf(acc[ii][jj], 0.f);
    __syncthreads();

    {
        float4 bv = *(const float4*)(b2 + 4 * j);
        #pragma unroll
        for (int ii = 0; ii < 4; ii++) {
            acc[ii][0] = bv.x; acc[ii][1] = bv.y; acc[ii][2] = bv.z; acc[ii][3] = bv.w;
        }
    }
    #pragma unroll 4
    for (int k = 0; k < 64; k++) {
        float4 ev = *(const float4*)(&h_t[k * TS + 4 * i]);
        float4 wv = __ldg((const float4*)(w2 + k * 64 + 4 * j));
        acc[0][0] = fmaf(ev.x, wv.x, acc[0][0]); acc[0][1] = fmaf(ev.x, wv.y, acc[0][1]);
        acc[0][2] = fmaf(ev.x, wv.z, acc[0][2]); acc[0][3] = fmaf(ev.x, wv.w, acc[0][3]);
        acc[1][0] = fmaf(ev.y, wv.x, acc[1][0]); acc[1][1] = fmaf(ev.y, wv.y, acc[1][1]);
        acc[1][2] = fmaf(ev.y, wv.z, acc[1][2]); acc[1][3] = fmaf(ev.y, wv.w, acc[1][3]);
        acc[2][0] = fmaf(ev.z, wv.x, acc[2][0]); acc[2][1] = fmaf(ev.z, wv.y, acc[2][1]);
        acc[2][2] = fmaf(ev.z, wv.z, acc[2][2]); acc[2][3] = fmaf(ev.z, wv.w, acc[2][3]);
        acc[3][0] = fmaf(ev.w, wv.x, acc[3][0]); acc[3][1] = fmaf(ev.w, wv.y, acc[3][1]);
        acc[3][2] = fmaf(ev.w, wv.z, acc[3][2]); acc[3][3] = fmaf(ev.w, wv.w, acc[3][3]);
    }
    #pragma unroll
    for (int ii = 0; ii < 4; ii++) {
        int eg = blockIdx.x * 32 + 4 * i + ii;
        if (eg < ne) {
            int dd = ei[ne + eg];
            float* dp = xw + (size_t)dd * 64 + 4 * j;
            atomicMaxF(dp + 0, acc[ii][0]);
            atomicMaxF(dp + 1, acc[ii][1]);
            atomicMaxF(dp + 2, acc[ii][2]);
            atomicMaxF(dp + 3, acc[ii][3]);
        }
    }
}

// ---------------------------------------------------------------------------
// k_fy: y = max(y, MLP_fy combined [xj, xi]) (128->64->64), xj=x[dst], xi=x[src]
// ---------------------------------------------------------------------------
__global__ __launch_bounds__(128) void k_fy(
        const int* __restrict__ ei,
        const float* __restrict__ b1,
        const float* __restrict__ w2, const float* __restrict__ b2,
        int buf, int ne) {
    __shared__ float in_t[128 * TS];
    __shared__ float h_t[64 * TS];
    int t = threadIdx.x;
    int q = t >> 5, el = t & 31;
    int e = blockIdx.x * 32 + el;
    const float* xr = g_x[buf];
    bool act = e < ne;
    int s = act ? ei[e] : 0;
    int d = act ? ei[ne + e] : 0;

    const float4* pj = (const float4*)(xr + (size_t)d * 64);
    const float4* pi = (const float4*)(xr + (size_t)s * 64);
    // 32 chunks (2 segments x 16), warp q handles chunks 8q..8q+7
    #pragma unroll
    for (int c0 = 0; c0 < 8; c0++) {
        int c = q * 8 + c0;
        int seg = c >> 4, r = c & 15;
        const float4* p = (seg == 0) ? pj : pi;
        float4 vv = act ? p[r] : make_float4(0, 0, 0, 0);
        int base = seg * 64 + 4 * r;
        in_t[(base + 0) * TS + el] = vv.x;
        in_t[(base + 1) * TS + el] = vv.y;
        in_t[(base + 2) * TS + el] = vv.z;
        in_t[(base + 3) * TS + el] = vv.w;
    }
    __syncthreads();

    int i = t & 7;
    int j = t >> 3;
    float acc[4][4];
    {
        float4 bv = *(const float4*)(b1 + 4 * j);
        #pragma unroll
        for (int ii = 0; ii < 4; ii++) {
            acc[ii][0] = bv.x; acc[ii][1] = bv.y; acc[ii][2] = bv.z; acc[ii][3] = bv.w;
        }
    }
    #pragma unroll 4
    for (int k = 0; k < 128; k++) {
        float4 ev = *(const float4*)(&in_t[k * TS + 4 * i]);
        float4 wv = __ldg((const float4*)(g_wfy + k * 64 + 4 * j));
        acc[0][0] = fmaf(ev.x, wv.x, acc[0][0]); acc[0][1] = fmaf(ev.x, wv.y, acc[0][1]);
        acc[0][2] = fmaf(ev.x, wv.z, acc[0][2]); acc[0][3] = fmaf(ev.x, wv.w, acc[0][3]);
        acc[1][0] = fmaf(ev.y, wv.x, acc[1][0]); acc[1][1] = fmaf(ev.y, wv.y, acc[1][1]);
        acc[1][2] = fmaf(ev.y, wv.z, acc[1][2]); acc[1][3] = fmaf(ev.y, wv.w, acc[1][3]);
        acc[2][0] = fmaf(ev.z, wv.x, acc[2][0]); acc[2][1] = fmaf(ev.z, wv.y, acc[2][1]);
        acc[2][2] = fmaf(ev.z, wv.z, acc[2][2]); acc[2][3] = fmaf(ev.z, wv.w, acc[2][3]);
        acc[3][0] = fmaf(ev.w, wv.x, acc[3][0]); acc[3][1] = fmaf(ev.w, wv.y, acc[3][1]);
        acc[3][2] = fmaf(ev.w, wv.z, acc[3][2]); acc[3][3] = fmaf(ev.w, wv.w, acc[3][3]);
    }
    #pragma unroll
    for (int jj = 0; jj < 4; jj++)
        #pragma unroll
        for (int ii = 0; ii < 4; ii++)
            h_t[(4 * j + jj) * TS + 4 * i + ii] = fmaxf(acc[ii][jj], 0.f);
    __syncthreads();

    {
        float4 bv = *(const float4*)(b2 + 4 * j);
        #pragma unroll
        for (int ii = 0; ii < 4; ii++) {
            acc[ii][0] = bv.x; acc[ii][1] = bv.y; acc[ii][2] = bv.z; acc[ii][3] = bv.w;
        }
    }
    #pragma unroll 4
    for (int k = 0; k < 64; k++) {
        float4 ev = *(const float4*)(&h_t[k * TS + 4 * i]);
        float4 wv = __ldg((const float4*)(w2 + k * 64 + 4 * j));
        acc[0][0] = fmaf(ev.x, wv.x, acc[0][0]); acc[0][1] = fmaf(ev.x, wv.y, acc[0][1]);
        acc[0][2] = fmaf(ev.x, wv.z, acc[0][2]); acc[0][3] = fmaf(ev.x, wv.w, acc[0][3]);
        acc[1][0] = fmaf(ev.y, wv.x, acc[1][0]); acc[1][1] = fmaf(ev.y, wv.y, acc[1][1]);
        acc[1][2] = fmaf(ev.y, wv.z, acc[1][2]); acc[1][3] = fmaf(ev.y, wv.w, acc[1][3]);
        acc[2][0] = fmaf(ev.z, wv.x, acc[2][0]); acc[2][1] = fmaf(ev.z, wv.y, acc[2][1]);
        acc[2][2] = fmaf(ev.z, wv.z, acc[2][2]); acc[2][3] = fmaf(ev.z, wv.w, acc[2][3]);
        acc[3][0] = fmaf(ev.w, wv.x, acc[3][0]); acc[3][1] = fmaf(ev.w, wv.y, acc[3][1]);
        acc[3][2] = fmaf(ev.w, wv.z, acc[3][2]); acc[3][3] = fmaf(ev.w, wv.w, acc[3][3]);
    }
    #pragma unroll
    for (int ii = 0; ii < 4; ii++) {
        int eg = blockIdx.x * 32 + 4 * i + ii;
        if (eg < ne) {
            float4* yp = (float4*)(g_y + (size_t)eg * 64 + 4 * j);
            float4 old = *yp;
            old.x = fmaxf(old.x, acc[ii][0]);
            old.y = fmaxf(old.y, acc[ii][1]);
            old.z = fmaxf(old.z, acc[ii][2]);
            old.w = fmaxf(old.w, acc[ii][3]);
            *yp = old;
        }
    }
}

// ---------------------------------------------------------------------------
// head: out = w3^T relu(w2^T relu(w1^T x + b1) + b2)
// 16 nodes/block, 16 threads/node, 4 cols/thread, shuffle-reduce
// ---------------------------------------------------------------------------
__global__ __launch_bounds__(256) void k_out(
        const float* __restrict__ w1, const float* __restrict__ b1,
        const float* __restrict__ w2, const float* __restrict__ b2,
        const float* __restrict__ w3, float* __restrict__ out,
        int buf, int n) {
    __shared__ float x_s[16][68];
    __shared__ float h_s[16][68];
    int g = threadIdx.x >> 4, tt = threadIdx.x & 15;
    int node = blockIdx.x * 16 + g;
    *(float4*)(&x_s[g][4 * tt]) = *(const float4*)(g_x[buf] + (size_t)node * 64 + 4 * tt);
    __syncthreads();
    const float4* w1v = (const float4*)w1;
    float4 acc = *(const float4*)(b1 + 4 * tt);
    #pragma unroll 8
    for (int k = 0; k < 64; k++) {
        float sv = x_s[g][k];
        float4 w = w1v[k * 16 + tt];
        acc.x = fmaf(sv, w.x, acc.x);
        acc.y = fmaf(sv, w.y, acc.y);
        acc.z = fmaf(sv, w.z, acc.z);
        acc.w = fmaf(sv, w.w, acc.w);
    }
    *(float4*)(&h_s[g][4 * tt]) = make_float4(fmaxf(acc.x, 0.f), fmaxf(acc.y, 0.f),
                                              fmaxf(acc.z, 0.f), fmaxf(acc.w, 0.f));
    __syncthreads();
    const float4* w2v = (const float4*)w2;
    float4 o = *(const float4*)(b2 + 4 * tt);
    #pragma unroll 8
    for (int k = 0; k < 64; k++) {
        float sv = h_s[g][k];
        float4 w = w2v[k * 16 + tt];
        o.x = fmaf(sv, w.x, o.x);
        o.y = fmaf(sv, w.y, o.y);
        o.z = fmaf(sv, w.z, o.z);
        o.w = fmaf(sv, w.w, o.w);
    }
    float4 w3v = *(const float4*)(w3 + 4 * tt);
    float p = fmaxf(o.x, 0.f) * w3v.x + fmaxf(o.y, 0.f) * w3v.y
            + fmaxf(o.z, 0.f) * w3v.z + fmaxf(o.w, 0.f) * w3v.w;
    #pragma unroll
    for (int sh = 8; sh > 0; sh >>= 1)
        p += __shfl_xor_sync(0xffffffffu, p, sh, 16);
    if (tt == 0) out[node] = p;
}

// ---------------------------------------------------------------------------
extern "C" void kernel_launch(void* const* d_in, const int* in_sizes, int n_in,
                              void* d_out, int out_size) {
    const float* v      = (const float*)d_in[0];
    const float* labels = (const float*)d_in[1];
    const int*   ei     = (const int*)d_in[2];
    // d_in[3] = loop (fixed at 3; unrolled below)
    const float *hx_w1 = (const float*)d_in[4],  *hx_b1 = (const float*)d_in[5];
    const float *hx_w2 = (const float*)d_in[6],  *hx_b2 = (const float*)d_in[7];
    const float *hy_w1 = (const float*)d_in[8],  *hy_b1 = (const float*)d_in[9];
    const float *hy_w2 = (const float*)d_in[10], *hy_b2 = (const float*)d_in[11];
    const float *fx_w1 = (const float*)d_in[12], *fx_b1 = (const float*)d_in[13];
    const float *fx_w2 = (const float*)d_in[14], *fx_b2 = (const float*)d_in[15];
    const float *fy_w1 = (const float*)d_in[16], *fy_b1 = (const float*)d_in[17];
    const float *fy_w2 = (const float*)d_in[18], *fy_b2 = (const float*)d_in[19];
    const float *fe_w1 = (const float*)d_in[20], *fe_b1 = (const float*)d_in[21];
    const float *fe_w2 = (const float*)d_in[22], *fe_b2 = (const float*)d_in[23];
    const float *fe_w3 = (const float*)d_in[24];

    int n  = in_sizes[0] / 7;       // 50000
    int ne = in_sizes[2] / 2;       // 250000
    float* out = (float*)d_out;

    k_goal<<<1, 1024>>>(v, labels, n);
    k_prep_fx<<<(192 * 64 + 255) / 256, 256>>>(fx_w1);
    k_prep_fy<<<(128 * 64 + 255) / 256, 256>>>(fy_w1);
    k_prep_h<<<37, 64>>>(hy_w1, hx_w1, hx_b1);

    k_x0<<<n / 4, 256>>>(v, labels, hx_w2, hx_b2, n);
    k_y0<<<ne / 16, 256>>>(v, labels, ei, hy_b1, hy_w2, hy_b2, ne);

    int copy_blocks = (n * 16 + 255) / 256;    // n*64/4 float4s
    int eb = (ne + 31) / 32;                    // 7813 blocks

    // iter 1: x_a(0) -> x_b(1)
    k_copy<<<copy_blocks, 256>>>(0, 1, n * 16);
    k_fx<<<eb, 128>>>(ei, fx_b1, fx_w2, fx_b2, 0, 1, ne);
    k_fy<<<eb, 128>>>(ei, fy_b1, fy_w2, fy_b2, 1, ne);
    // iter 2: x_b(1) -> x_a(0)
    k_copy<<<copy_blocks, 256>>>(1, 0, n * 16);
    k_fx<<<eb, 128>>>(ei, fx_b1, fx_w2, fx_b2, 1, 0, ne);
    k_fy<<<eb, 128>>>(ei, fy_b1, fy_w2, fy_b2, 0, ne);
    // iter 3: x_a(0) -> x_b(1)
    k_copy<<<copy_blocks, 256>>>(0, 1, n * 16);
    k_fx<<<eb, 128>>>(ei, fx_b1, fx_w2, fx_b2, 0, 1, ne);
    k_fy<<<eb, 128>>>(ei, fy_b1, fy_w2, fy_b2, 1, ne);

    k_out<<<n / 16, 256>>>(fe_w1, fe_b1, fe_w2, fe_b2, fe_w3, out, 1, n);
}